// round 2
// baseline (speedup 1.0000x reference)
#include <cuda_runtime.h>

#define BB 2
#define QQ 8192
#define MM 65536

__device__ float g_feat[BB * 64 * 64 * 64];     // channel-last [b][y][x][c]
__device__ float g_X[MM * 4];
__device__ int   g_gidx[MM];
__device__ float g_score[MM];
__device__ float g_H1[(size_t)MM * 256];
__device__ float g_H2[(size_t)MM * 256];

__device__ __forceinline__ float fast_gelu(float x) {
    float u = 1.5957691216057308f * fmaf(0.044715f * x * x, x, x);
    return x * __fdividef(1.0f, 1.0f + __expf(-u));
}

// K1: conv3x3 SAME + bias, write channel-last feat
__global__ void conv_kernel(const float* __restrict__ inp,
                            const float* __restrict__ w,
                            const float* __restrict__ bias) {
    __shared__ float s_in[27];
    int pix = blockIdx.x;
    int b = pix >> 12, y = (pix >> 6) & 63, x = pix & 63;
    int c = threadIdx.x;
    if (c < 27) {
        int i = c / 9, kk = c - i * 9;
        int yy = y + kk / 3 - 1, xx = x + (kk % 3) - 1;
        float v = 0.f;
        if (yy >= 0 && yy < 64 && xx >= 0 && xx < 64)
            v = inp[((b * 3 + i) * 64 + yy) * 64 + xx];
        s_in[c] = v;
    }
    __syncthreads();
    float acc = bias[c];
#pragma unroll
    for (int t = 0; t < 27; t++) acc = fmaf(s_in[t], w[c * 27 + t], acc);
    g_feat[(pix << 6) + c] = acc;
}

// K2: per query-shift prep + score MLP (2->256->1)
__global__ void prep_kernel(const float* __restrict__ coord,
                            const float* __restrict__ scale,
                            const float* __restrict__ sw0,
                            const float* __restrict__ sb0,
                            const float* __restrict__ sw1,
                            const float* __restrict__ sb1) {
    int m = blockIdx.x * blockDim.x + threadIdx.x;
    if (m >= MM) return;
    int b = m >> 15, q = (m >> 2) & (QQ - 1), s = m & 3;
    float vx = (s < 2) ? -1.f : 1.f;
    float vy = (s & 1) ? 1.f : -1.f;

    float c0 = coord[(b * QQ + q) * 2 + 0];
    float c1 = coord[(b * QQ + q) * 2 + 1];
    float tx = 63.0f / (1.0f - scale[(size_t)b * QQ * 2 + 0]);
    float ty = 63.0f / (1.0f - scale[(size_t)b * QQ * 2 + 1]);
    float sh0 = vx * (1.0f / tx) + 1e-6f;
    float sh1 = vy * (1.0f / ty) + 1e-6f;

    float cc0 = fminf(fmaxf(c0 + sh0, -1.0f + 1e-6f), 1.0f - 1e-6f);
    float cc1 = fminf(fmaxf(c1 + sh1, -1.0f + 1e-6f), 1.0f - 1e-6f);
    int iy = (int)fminf(fmaxf(rintf((cc0 + 1.0f) * 32.0f - 0.5f), 0.f), 63.f);
    int ix = (int)fminf(fmaxf(rintf((cc1 + 1.0f) * 32.0f - 0.5f), 0.f), 63.f);

    float ck0 = -1.0f + (float)(2 * iy + 1) * 0.015625f;
    float ck1 = -1.0f + (float)(2 * ix + 1) * 0.015625f;
    float relx = (c0 - ck0) * 64.0f;
    float rely = (c1 - ck1) * 64.0f;
    float st0 = scale[(size_t)(b * QQ + q) * 2 + 0] * 64.0f;
    float st1 = scale[(size_t)(b * QQ + q) * 2 + 1] * 64.0f;

    float acc = 0.f;
    for (int j = 0; j < 256; j++) {
        float h = fast_gelu(fmaf(relx, sw0[j], fmaf(rely, sw0[256 + j], sb0[j])));
        acc = fmaf(h, sw1[j], acc);
    }
    g_score[m] = acc + sb1[0];
    *(float4*)(g_X + m * 4) = make_float4(relx, rely, st0, st1);
    g_gidx[m] = iy * 64 + ix;
}

// K3: H1 = gelu(X @ iw0 + ib0)
__global__ void h1_kernel(const float* __restrict__ iw0, const float* __restrict__ ib0) {
    size_t gid = (size_t)blockIdx.x * 256 + threadIdx.x;
    int m = (int)(gid >> 8), j = (int)(gid & 255);
    float4 x = *(const float4*)(g_X + (size_t)m * 4);
    float a = ib0[j];
    a = fmaf(x.x, iw0[j], a);
    a = fmaf(x.y, iw0[256 + j], a);
    a = fmaf(x.z, iw0[512 + j], a);
    a = fmaf(x.w, iw0[768 + j], a);
    g_H1[gid] = fast_gelu(a);
}

// K4: H2 = gelu(H1 @ iw1 + ib1)   M=65536 K=256 N=256
__global__ void h2_kernel(const float* __restrict__ iw1, const float* __restrict__ ib1) {
    __shared__ float a_s[32 * 32];
    __shared__ float b_s[32 * 256];
    int tid = threadIdx.x;
    int m0 = blockIdx.x << 5;
    int ni = tid & 31, mig = tid >> 5;

    float acc[4][8];
#pragma unroll
    for (int a = 0; a < 4; a++)
#pragma unroll
        for (int c = 0; c < 8; c++) acc[a][c] = 0.f;

    for (int k0 = 0; k0 < 256; k0 += 32) {
        __syncthreads();
        {
            int mm = tid >> 3, kf = (tid & 7) << 2;
            *(float4*)(a_s + mm * 32 + kf) =
                *(const float4*)(g_H1 + (size_t)(m0 + mm) * 256 + k0 + kf);
        }
#pragma unroll
        for (int r = 0; r < 8; r++) {
            int f4 = (r << 8) + tid;
            int kk = f4 >> 6, nn = (f4 & 63) << 2;
            *(float4*)(b_s + kk * 256 + nn) =
                *(const float4*)(iw1 + (size_t)(k0 + kk) * 256 + nn);
        }
        __syncthreads();
#pragma unroll
        for (int kk = 0; kk < 32; kk++) {
            float av[4];
#pragma unroll
            for (int a = 0; a < 4; a++) av[a] = a_s[((mig << 2) + a) * 32 + kk];
            float4 b0 = *(float4*)(b_s + kk * 256 + (ni << 2));
            float4 b1 = *(float4*)(b_s + kk * 256 + 128 + (ni << 2));
            float bv[8] = {b0.x, b0.y, b0.z, b0.w, b1.x, b1.y, b1.z, b1.w};
#pragma unroll
            for (int a = 0; a < 4; a++)
#pragma unroll
                for (int c = 0; c < 8; c++) acc[a][c] = fmaf(av[a], bv[c], acc[a][c]);
        }
    }
#pragma unroll
    for (int a = 0; a < 4; a++) {
        size_t m = m0 + (mig << 2) + a;
        float4 o0, o1;
        o0.x = fast_gelu(acc[a][0] + ib1[(ni << 2) + 0]);
        o0.y = fast_gelu(acc[a][1] + ib1[(ni << 2) + 1]);
        o0.z = fast_gelu(acc[a][2] + ib1[(ni << 2) + 2]);
        o0.w = fast_gelu(acc[a][3] + ib1[(ni << 2) + 3]);
        o1.x = fast_gelu(acc[a][4] + ib1[128 + (ni << 2) + 0]);
        o1.y = fast_gelu(acc[a][5] + ib1[128 + (ni << 2) + 1]);
        o1.z = fast_gelu(acc[a][6] + ib1[128 + (ni << 2) + 2]);
        o1.w = fast_gelu(acc[a][7] + ib1[128 + (ni << 2) + 3]);
        *(float4*)(g_H2 + m * 256 + (ni << 2)) = o0;
        *(float4*)(g_H2 + m * 256 + 128 + (ni << 2)) = o1;
    }
}

// K5: fused wrow = H2@iw2+ib2 ; pred = value.wrow + score ; out = weightMLP(pred)
__global__ void big_kernel(const float* __restrict__ iw2, const float* __restrict__ ib2,
                           const float* __restrict__ ww0, const float* __restrict__ wb0,
                           const float* __restrict__ ww1, const float* __restrict__ wb1,
                           float* __restrict__ out) {
    extern __shared__ float sm[];
    float* val_s = sm;                 // 32*576
    float* h2_s  = sm + 18432;         // 32*256
    float* w_s   = sm + 26624;         // 32*128
    float* pred_s = sm + 30720;        // 96
    float* score_s = sm + 30816;       // 32
    int*   gidx_s  = (int*)(sm + 30848); // 32

    int tid = threadIdx.x;
    int m0 = blockIdx.x << 5;
    int b = m0 >> 15;

    if (tid < 32) {
        gidx_s[tid] = g_gidx[m0 + tid];
        score_s[tid] = g_score[m0 + tid];
    }
    __syncthreads();

    // gather value: 32 q x 9 neighbors x 64 ch
    for (int wi = tid; wi < 4608; wi += 256) {
        int seg = wi >> 4, f4 = wi & 15;
        int mi = seg / 9, kk = seg - mi * 9;
        int g = gidx_s[mi];
        int yy = (g >> 6) + kk / 3 - 1;
        int xx = (g & 63) + (kk % 3) - 1;
        float4 v = make_float4(0.f, 0.f, 0.f, 0.f);
        if (yy >= 0 && yy < 64 && xx >= 0 && xx < 64)
            v = *(const float4*)(g_feat + (size_t)(((b * 64 + yy) * 64 + xx) << 6) + (f4 << 2));
        *(float4*)(val_s + mi * 576 + (kk << 6) + (f4 << 2)) = v;
    }
    for (int i = tid; i < 2048; i += 256)
        *(float4*)(h2_s + (i << 2)) = *(const float4*)(g_H2 + ((size_t)m0 << 8) + ((size_t)i << 2));

    int ni = tid & 31, mig = tid >> 5;
    float po[4][3];
#pragma unroll
    for (int a = 0; a < 4; a++)
#pragma unroll
        for (int c = 0; c < 3; c++) po[a][c] = 0.f;

    for (int nb = 0; nb < 14; nb++) {
        int nbase = nb << 7;
        float acc[4][4];
#pragma unroll
        for (int a = 0; a < 4; a++)
#pragma unroll
            for (int c = 0; c < 4; c++) acc[a][c] = 0.f;

        for (int k0 = 0; k0 < 256; k0 += 32) {
            __syncthreads();
#pragma unroll
            for (int r = 0; r < 4; r++) {
                int i = (r << 8) + tid;
                int kk = i >> 5, nf = (i & 31) << 2;
                int n = nbase + nf;
                float4 v = make_float4(0.f, 0.f, 0.f, 0.f);
                if (n < 1728)
                    v = *(const float4*)(iw2 + (size_t)(k0 + kk) * 1728 + n);
                *(float4*)(w_s + (kk << 7) + nf) = v;
            }
            __syncthreads();
#pragma unroll
            for (int kk = 0; kk < 32; kk++) {
                float av[4];
#pragma unroll
                for (int a = 0; a < 4; a++)
                    av[a] = h2_s[((mig << 2) + a) * 256 + k0 + kk];
                float4 bb = *(float4*)(w_s + (kk << 7) + (ni << 2));
                float bv[4] = {bb.x, bb.y, bb.z, bb.w};
#pragma unroll
                for (int a = 0; a < 4; a++)
#pragma unroll
                    for (int c = 0; c < 4; c++) acc[a][c] = fmaf(av[a], bv[c], acc[a][c]);
            }
        }
        // fused contraction epilogue
#pragma unroll
        for (int in = 0; in < 4; in++) {
            int n = nbase + (ni << 2) + in;
            if (n < 1728) {
                float bias = ib2[n];
                int cf = n / 3, kcol = n - cf * 3;
                int ch = cf / 9, k9 = cf - ch * 9;
                int voff = (k9 << 6) + ch;
#pragma unroll
                for (int a = 0; a < 4; a++) {
                    float wv = acc[a][in] + bias;
                    float vv = val_s[((mig << 2) + a) * 576 + voff];
                    float p = wv * vv;
                    if (kcol == 0) po[a][0] += p;
                    else if (kcol == 1) po[a][1] += p;
                    else po[a][2] += p;
                }
            }
        }
    }

    // warp-reduce over ni (lane), write pred (+score)
#pragma unroll
    for (int a = 0; a < 4; a++)
#pragma unroll
        for (int c = 0; c < 3; c++) {
            float v = po[a][c];
#pragma unroll
            for (int o = 16; o; o >>= 1) v += __shfl_xor_sync(0xffffffffu, v, o);
            if (ni == 0) pred_s[((mig << 2) + a) * 3 + c] = v + score_s[(mig << 2) + a];
        }
    __syncthreads();

    // fused weight MLP: 8 queries x 3 outputs
    if (tid < 24) {
        int qi = tid / 3, k = tid - qi * 3;
        int base = qi * 12 + k;
        float x0 = pred_s[base], x1 = pred_s[base + 3];
        float x2 = pred_s[base + 6], x3 = pred_s[base + 9];
        float acc = wb1[0];
        for (int j = 0; j < 256; j++) {
            float h = fast_gelu(fmaf(x0, ww0[j],
                        fmaf(x1, ww0[256 + j],
                        fmaf(x2, ww0[512 + j],
                        fmaf(x3, ww0[768 + j], wb0[j])))));
            acc = fmaf(h, ww1[j], acc);
        }
        out[((m0 >> 2) + qi) * 3 + k] = acc;
    }
}

extern "C" void kernel_launch(void* const* d_in, const int* in_sizes, int n_in,
                              void* d_out, int out_size) {
    const float* inp   = (const float*)d_in[0];
    const float* coord = (const float*)d_in[1];
    const float* scale = (const float*)d_in[2];
    const float* enc_w = (const float*)d_in[3];
    const float* enc_b = (const float*)d_in[4];
    const float* iw0 = (const float*)d_in[5];
    const float* ib0 = (const float*)d_in[6];
    const float* iw1 = (const float*)d_in[7];
    const float* ib1 = (const float*)d_in[8];
    const float* iw2 = (const float*)d_in[9];
    const float* ib2 = (const float*)d_in[10];
    const float* sw0 = (const float*)d_in[11];
    const float* sb0 = (const float*)d_in[12];
    const float* sw1 = (const float*)d_in[13];
    const float* sb1 = (const float*)d_in[14];
    const float* ww0 = (const float*)d_in[15];
    const float* wb0 = (const float*)d_in[16];
    const float* ww1 = (const float*)d_in[17];
    const float* wb1 = (const float*)d_in[18];
    float* out = (float*)d_out;

    static int smem_set = 0;
    if (!smem_set) {
        cudaFuncSetAttribute(big_kernel, cudaFuncAttributeMaxDynamicSharedMemorySize, 123520);
        smem_set = 1;
    }

    conv_kernel<<<8192, 64>>>(inp, enc_w, enc_b);
    prep_kernel<<<256, 256>>>(coord, scale, sw0, sb0, sw1, sb1);
    h1_kernel<<<65536, 256>>>(iw0, ib0);
    h2_kernel<<<2048, 256>>>(iw1, ib1);
    big_kernel<<<2048, 256, 123520>>>(iw2, ib2, ww0, wb0, ww1, wb1, out);
}